// round 1
// baseline (speedup 1.0000x reference)
#include <cuda_runtime.h>
#include <float.h>
#include <math.h>

#define DMODEL 512
#define NHEAD  8
#define HDIM   64
#define BATCH  4
#define SEQ    2048

// Scratch (allocation-free rule: __device__ globals)
__device__ float g_q[BATCH * DMODEL * SEQ];
__device__ float g_k[BATCH * DMODEL * SEQ];
__device__ float g_v[BATCH * DMODEL * SEQ];
__device__ float g_x[BATCH * DMODEL * SEQ];

// ---------------------------------------------------------------------------
// Projection GEMM: Y[o][n] = sum_i W[o][i] * X[i][n] + bias[o]
// Tile: 128(o) x 128(n), k-step 16. 256 threads, 8x8 microtile per thread.
// ---------------------------------------------------------------------------
__device__ __forceinline__ void proj_tile(const float* __restrict__ Xb,
                                          const float* __restrict__ W,
                                          const float* __restrict__ bias,
                                          float* __restrict__ Yb) {
    __shared__ float Ws[128 * 16];   // [o][i], stride 16
    __shared__ float Xs[16 * 128];   // [i][n], stride 128

    const int tid = threadIdx.x;
    const int tx = tid & 15;
    const int ty = tid >> 4;
    const int n0 = blockIdx.x * 128;
    const int o0 = blockIdx.y * 128;

    float acc[8][8];
#pragma unroll
    for (int j = 0; j < 8; j++)
#pragma unroll
        for (int i = 0; i < 8; i++) acc[j][i] = 0.f;

    const int wo  = tid >> 2;        // 0..63
    const int wi4 = (tid & 3) * 4;   // 0,4,8,12
    const int xi  = tid >> 5;        // 0..7
    const int xn4 = (tid & 31) * 4;  // 0..124

    for (int k0 = 0; k0 < DMODEL; k0 += 16) {
        float4 w0 = *(const float4*)&W[(size_t)(o0 + wo) * DMODEL + k0 + wi4];
        float4 w1 = *(const float4*)&W[(size_t)(o0 + wo + 64) * DMODEL + k0 + wi4];
        float4 x0 = *(const float4*)&Xb[(size_t)(k0 + xi) * SEQ + n0 + xn4];
        float4 x1 = *(const float4*)&Xb[(size_t)(k0 + xi + 8) * SEQ + n0 + xn4];
        __syncthreads();   // previous iteration's compute done before overwrite
        *(float4*)&Ws[wo * 16 + wi4]        = w0;
        *(float4*)&Ws[(wo + 64) * 16 + wi4] = w1;
        *(float4*)&Xs[xi * 128 + xn4]       = x0;
        *(float4*)&Xs[(xi + 8) * 128 + xn4] = x1;
        __syncthreads();
#pragma unroll
        for (int i = 0; i < 16; i++) {
            float a[8];
#pragma unroll
            for (int j = 0; j < 8; j++) a[j] = Ws[(ty * 8 + j) * 16 + i];
            float4 b0 = *(float4*)&Xs[i * 128 + tx * 8];
            float4 b1 = *(float4*)&Xs[i * 128 + tx * 8 + 4];
            float bb[8] = {b0.x, b0.y, b0.z, b0.w, b1.x, b1.y, b1.z, b1.w};
#pragma unroll
            for (int j = 0; j < 8; j++)
#pragma unroll
                for (int c = 0; c < 8; c++) acc[j][c] += a[j] * bb[c];
        }
    }

#pragma unroll
    for (int j = 0; j < 8; j++) {
        const int o = o0 + ty * 8 + j;
        const float bv = bias[o];
        float4 r0 = make_float4(acc[j][0] + bv, acc[j][1] + bv, acc[j][2] + bv, acc[j][3] + bv);
        float4 r1 = make_float4(acc[j][4] + bv, acc[j][5] + bv, acc[j][6] + bv, acc[j][7] + bv);
        *(float4*)&Yb[(size_t)o * SEQ + n0 + tx * 8]     = r0;
        *(float4*)&Yb[(size_t)o * SEQ + n0 + tx * 8 + 4] = r1;
    }
}

__global__ void __launch_bounds__(256)
proj_qkv_kernel(const float* __restrict__ q, const float* __restrict__ k,
                const float* __restrict__ v,
                const float* __restrict__ Wq, const float* __restrict__ bq,
                const float* __restrict__ Wk, const float* __restrict__ bk,
                const float* __restrict__ Wv, const float* __restrict__ bv) {
    const int b = blockIdx.z & 3;
    const int which = blockIdx.z >> 2;   // 0:q 1:k 2:v
    const float* X; const float* W; const float* bias; float* Y;
    if (which == 0)      { X = q; W = Wq; bias = bq; Y = g_q; }
    else if (which == 1) { X = k; W = Wk; bias = bk; Y = g_k; }
    else                 { X = v; W = Wv; bias = bv; Y = g_v; }
    const size_t off = (size_t)b * DMODEL * SEQ;
    proj_tile(X + off, W, bias, Y + off);
}

__global__ void __launch_bounds__(256)
proj_out_kernel(const float* __restrict__ Wm, const float* __restrict__ bm,
                float* __restrict__ out) {
    const int b = blockIdx.z;
    const size_t off = (size_t)b * DMODEL * SEQ;
    proj_tile(g_x + off, Wm, bm, out + off);
}

// ---------------------------------------------------------------------------
// Flash attention: per CTA handles (b, h, 64 q-rows). head channel c = d*8+h.
// Streams 32 kv-tiles of 64. Online softmax, exact -FLT_MAX masking to match
// reference semantics (fully-masked rows -> uniform, same as jax softmax).
// ---------------------------------------------------------------------------
__global__ void __launch_bounds__(256)
attn_kernel(const int* __restrict__ Mmask) {
    extern __shared__ float sm[];
    float* Qs = sm;                    // [d][n]  64*64
    float* Ks = sm + 4096;             // [d][m]  64*64
    float* Vt = sm + 8192;             // [m][d]  stride 65 (conflict dodge)
    float* Ps = sm + 8192 + 64 * 65;   // [n][m]  64*64

    const int tid = threadIdx.x;
    const int tx = tid & 15;           // m-cols / d-cols (x4)
    const int ty = tid >> 4;           // n-rows (x4)
    const int n0 = blockIdx.x * 64;
    const int b = blockIdx.y >> 3;
    const int h = blockIdx.y & 7;

    const float* Qb = g_q + (size_t)b * DMODEL * SEQ;
    const float* Kb = g_k + (size_t)b * DMODEL * SEQ;
    const float* Vb = g_v + (size_t)b * DMODEL * SEQ;

    const int ld  = tid >> 4;          // 0..15
    const int lm4 = (tid & 15) * 4;

    // Load Q tile once: Qs[d][n]
#pragma unroll
    for (int r = 0; r < 4; r++) {
        const int dd = ld + 16 * r;
        float4 qv = *(const float4*)&Qb[(size_t)(dd * 8 + h) * SEQ + n0 + lm4];
        *(float4*)&Qs[dd * 64 + lm4] = qv;
    }

    float acc[4][4];
    float mrun[4], lrun[4];
#pragma unroll
    for (int r = 0; r < 4; r++) {
        mrun[r] = -FLT_MAX;
        lrun[r] = 0.f;
#pragma unroll
        for (int i = 0; i < 4; i++) acc[r][i] = 0.f;
    }

    for (int mt = 0; mt < 32; mt++) {
        const int m0 = mt * 64;

        float4 kreg[4], vreg[4];
#pragma unroll
        for (int r = 0; r < 4; r++) {
            const int dd = ld + 16 * r;
            kreg[r] = *(const float4*)&Kb[(size_t)(dd * 8 + h) * SEQ + m0 + lm4];
            vreg[r] = *(const float4*)&Vb[(size_t)(dd * 8 + h) * SEQ + m0 + lm4];
        }
        __syncthreads();   // previous tile's compute (Ks/Vt/Ps reads) done
#pragma unroll
        for (int r = 0; r < 4; r++) {
            const int dd = ld + 16 * r;
            *(float4*)&Ks[dd * 64 + lm4] = kreg[r];
            Vt[(lm4 + 0) * 65 + dd] = vreg[r].x;
            Vt[(lm4 + 1) * 65 + dd] = vreg[r].y;
            Vt[(lm4 + 2) * 65 + dd] = vreg[r].z;
            Vt[(lm4 + 3) * 65 + dd] = vreg[r].w;
        }
        __syncthreads();

        // S = Q^T K  (4x4 microtile per thread)
        float s[4][4];
#pragma unroll
        for (int r = 0; r < 4; r++)
#pragma unroll
            for (int i = 0; i < 4; i++) s[r][i] = 0.f;

#pragma unroll 8
        for (int d = 0; d < 64; d++) {
            float4 qv = *(float4*)&Qs[d * 64 + ty * 4];
            float4 kv = *(float4*)&Ks[d * 64 + tx * 4];
            float qa[4] = {qv.x, qv.y, qv.z, qv.w};
            float ka[4] = {kv.x, kv.y, kv.z, kv.w};
#pragma unroll
            for (int r = 0; r < 4; r++)
#pragma unroll
                for (int i = 0; i < 4; i++) s[r][i] += qa[r] * ka[i];
        }

        // scale + mask + online softmax
        const float scale = 0.125f;   // 1/sqrt(64)
#pragma unroll
        for (int r = 0; r < 4; r++) {
            const int n = n0 + ty * 4 + r;
            int4 mv = *(const int4*)&Mmask[((size_t)b * SEQ + n) * SEQ + m0 + tx * 4];
            s[r][0] = mv.x ? s[r][0] * scale : -FLT_MAX;
            s[r][1] = mv.y ? s[r][1] * scale : -FLT_MAX;
            s[r][2] = mv.z ? s[r][2] * scale : -FLT_MAX;
            s[r][3] = mv.w ? s[r][3] * scale : -FLT_MAX;

            float mx = fmaxf(fmaxf(s[r][0], s[r][1]), fmaxf(s[r][2], s[r][3]));
#pragma unroll
            for (int off = 8; off >= 1; off >>= 1)
                mx = fmaxf(mx, __shfl_xor_sync(0xffffffffu, mx, off));

            const float nm = fmaxf(mrun[r], mx);
            const float alpha = __expf(mrun[r] - nm);
            mrun[r] = nm;

            float4 p;
            p.x = __expf(s[r][0] - nm);
            p.y = __expf(s[r][1] - nm);
            p.z = __expf(s[r][2] - nm);
            p.w = __expf(s[r][3] - nm);
            *(float4*)&Ps[(ty * 4 + r) * 64 + tx * 4] = p;

            float psum = p.x + p.y + p.z + p.w;
#pragma unroll
            for (int off = 8; off >= 1; off >>= 1)
                psum += __shfl_xor_sync(0xffffffffu, psum, off);

            lrun[r] = lrun[r] * alpha + psum;
#pragma unroll
            for (int i = 0; i < 4; i++) acc[r][i] *= alpha;
        }
        __syncthreads();   // Ps fully written before cross-thread reads

        // O += P @ V^T   (acc[n][d])
#pragma unroll 8
        for (int m = 0; m < 64; m++) {
            float pv[4], vv[4];
#pragma unroll
            for (int r = 0; r < 4; r++) pv[r] = Ps[(ty * 4 + r) * 64 + m];
#pragma unroll
            for (int i = 0; i < 4; i++) vv[i] = Vt[m * 65 + tx * 4 + i];
#pragma unroll
            for (int r = 0; r < 4; r++)
#pragma unroll
                for (int i = 0; i < 4; i++) acc[r][i] += pv[r] * vv[i];
        }
        // loop-top __syncthreads() orders this against next tile's smem writes
    }

    // normalize and write x[b][d*8+h][n]
#pragma unroll
    for (int r = 0; r < 4; r++) {
        const float inv = 1.f / lrun[r];
        const int n = n0 + ty * 4 + r;
#pragma unroll
        for (int i = 0; i < 4; i++) {
            const int d = tx * 4 + i;
            g_x[((size_t)b * DMODEL + d * 8 + h) * SEQ + n] = acc[r][i] * inv;
        }
    }
}

// ---------------------------------------------------------------------------
extern "C" void kernel_launch(void* const* d_in, const int* in_sizes, int n_in,
                              void* d_out, int out_size) {
    const float* q  = (const float*)d_in[0];
    const float* k  = (const float*)d_in[1];
    const float* v  = (const float*)d_in[2];
    const int*   Mm = (const int*)  d_in[3];
    const float* Wq = (const float*)d_in[4];
    const float* bq = (const float*)d_in[5];
    const float* Wk = (const float*)d_in[6];
    const float* bk = (const float*)d_in[7];
    const float* Wv = (const float*)d_in[8];
    const float* bv = (const float*)d_in[9];
    const float* Wm = (const float*)d_in[10];
    const float* bm = (const float*)d_in[11];
    float* out = (float*)d_out;

    // 1) fused QKV projections
    dim3 gqkv(SEQ / 128, DMODEL / 128, 3 * BATCH);
    proj_qkv_kernel<<<gqkv, 256>>>(q, k, v, Wq, bq, Wk, bk, Wv, bv);

    // 2) flash attention
    const int smem_bytes = (4096 * 2 + 64 * 65 + 4096) * (int)sizeof(float); // Qs,Ks,Vt,Ps
    cudaFuncSetAttribute(attn_kernel, cudaFuncAttributeMaxDynamicSharedMemorySize, smem_bytes);
    dim3 gattn(SEQ / 64, BATCH * NHEAD);
    attn_kernel<<<gattn, 256, smem_bytes>>>(Mm);

    // 3) output projection
    dim3 gout(SEQ / 128, DMODEL / 128, BATCH);
    proj_out_kernel<<<gout, 256>>>(Wm, bm, out);
}